// round 15
// baseline (speedup 1.0000x reference)
#include <cuda_runtime.h>
#include <cuda_bf16.h>
#include <math.h>
#include <stdint.h>

// Problem dims
#define B_   1024
#define H1   500
#define IN_  784
#define NOUT 10
#define T_   100
#define NP   512

// combined operand width = 6 * K0P  (col [0,K0P) = integer pass-0,
// cols [(1+g)*K0P,(2+g)*K0P) = correction group g, g=0..4)
#define K0P1 832               // 784 -> 13*64
#define KC1  4992              // 6*832 = 39*128
#define K0P2 512               // 500 -> 8*64
#define KC2  3072              // 6*512 = 24*128

// ---------------- device scratch ----------------
__device__ __align__(16) __nv_bfloat16 g_ca1[(size_t)B_ * KC1];
__device__ __align__(16) __nv_bfloat16 g_cw1[(size_t)NP * KC1];
__device__ __align__(16) __nv_bfloat16 g_ca2[(size_t)B_ * KC2];
__device__ __align__(16) __nv_bfloat16 g_cw2[(size_t)NP * KC2];
__device__ float g_sa1[B_], g_sw1[NP], g_sa2[B_], g_sw2[NP];
__device__ float g_h[B_ * H1];
__device__ float g_drive[B_ * H1];
__device__ float g_cf[T_];

// ---------------- helpers ----------------
#define SW128(o) ((o) ^ (((o) >> 3) & 0x70))

__device__ __forceinline__ uint32_t smem_u32(const void* p) {
    uint32_t a;
    asm("{ .reg .u64 t; cvta.to.shared.u64 t, %1; cvt.u32.u64 %0, t; }"
        : "=r"(a) : "l"(p));
    return a;
}
__device__ __forceinline__ void cp_async16(uint32_t dst, const void* src) {
    asm volatile("cp.async.cg.shared.global [%0], [%1], 16;"
                 :: "r"(dst), "l"(src));
}
#define CP_COMMIT()  asm volatile("cp.async.commit_group;" ::: "memory")
#define CP_WAIT(n)   asm volatile("cp.async.wait_group %0;" :: "n"(n) : "memory")

__device__ __forceinline__ void ldm_x4(uint32_t& r0, uint32_t& r1,
                                       uint32_t& r2, uint32_t& r3, uint32_t addr) {
    asm volatile("ldmatrix.sync.aligned.m8n8.x4.shared.b16 {%0,%1,%2,%3}, [%4];"
                 : "=r"(r0), "=r"(r1), "=r"(r2), "=r"(r3) : "r"(addr));
}
__device__ __forceinline__ void ldm_x2(uint32_t& r0, uint32_t& r1, uint32_t addr) {
    asm volatile("ldmatrix.sync.aligned.m8n8.x2.shared.b16 {%0,%1}, [%2];"
                 : "=r"(r0), "=r"(r1) : "r"(addr));
}
__device__ __forceinline__ void mma16816(float* c, const uint32_t* a, const uint32_t* b) {
    asm volatile("mma.sync.aligned.m16n8k16.row.col.f32.bf16.bf16.f32 "
                 "{%0,%1,%2,%3}, {%4,%5,%6,%7}, {%8,%9}, {%0,%1,%2,%3};"
                 : "+f"(c[0]), "+f"(c[1]), "+f"(c[2]), "+f"(c[3])
                 : "r"(a[0]), "r"(a[1]), "r"(a[2]), "r"(a[3]),
                   "r"(b[0]), "r"(b[1]));
}

// ---------------- integer limb extraction (proven exact) --------------------
__device__ __forceinline__ void limbs_of(float a, float qs,
                                         float& A0, float& A1, float& A2) {
    const float q = a * qs;
    A0 = rintf(q);
    const float r1 = q - A0;
    const float t1 = r1 * 256.0f;
    A1 = rintf(t1);
    const float r2 = t1 - A1;
    A2 = rintf(r2 * 256.0f);
}

// Row converter -> combined buffer (width 6*K0P).
// A-side groups: [L0, L1, L1, L0, L2]; B-side: [L1, L0, L1, L2, L0]
// (products per group: L0*L1, L1*L0, L1*L1, L0*L2, L2*L0 — proven set).
template<int KD, int K0P, bool ISA>
__device__ void conv_row_body(const float* __restrict__ gsrc, int valid,
                              __nv_bfloat16* __restrict__ pc,
                              float* __restrict__ sarr, int ridx,
                              float* __restrict__ srow, float* __restrict__ red) {
    const int tid = threadIdx.x;  // 256
    float mx = 0.0f;
    for (int k = tid; k < KD; k += 256) {
        const float a = valid ? gsrc[k] : 0.0f;
        srow[k] = a;
        mx = fmaxf(mx, fabsf(a));
    }
    red[tid] = mx;
    __syncthreads();
    for (int s = 128; s; s >>= 1) {
        if (tid < s) red[tid] = fmaxf(red[tid], red[tid + s]);
        __syncthreads();
    }
    const float rm = red[0];
    int e = 0;
    if (rm > 0.0f) frexpf(rm, &e);
    if (tid == 0) sarr[ridx] = ldexpf(1.0f, e - 8);
    const float qs = ldexpf(1.0f, 8 - e);
    const float s0 = ldexpf(1.0f, e - 8);
    const float s1 = ldexpf(1.0f, e - 16);
    const float s2 = ldexpf(1.0f, e - 24);

    const __nv_bfloat16 z = __float2bfloat16(0.0f);
    for (int k = tid; k < K0P; k += 256) {
        if (k < KD) {
            float A0, A1, A2;
            limbs_of(srow[k], qs, A0, A1, A2);          // once per element
            pc[k] = __float2bfloat16(A0);                // pass-0 integer
            const __nv_bfloat16 L0 = __float2bfloat16(A0 * s0);
            const __nv_bfloat16 L1 = __float2bfloat16(A1 * s1);
            const __nv_bfloat16 L2 = __float2bfloat16(A2 * s2);
            if (ISA) {
                pc[1 * K0P + k] = L0; pc[2 * K0P + k] = L1;
                pc[3 * K0P + k] = L1; pc[4 * K0P + k] = L0;
                pc[5 * K0P + k] = L2;
            } else {
                pc[1 * K0P + k] = L1; pc[2 * K0P + k] = L0;
                pc[3 * K0P + k] = L1; pc[4 * K0P + k] = L2;
                pc[5 * K0P + k] = L0;
            }
        } else {
#pragma unroll
            for (int g = 0; g < 6; g++) pc[g * K0P + k] = z;
        }
    }
}

// Merged input conversions: x rows, w1 rows, w2 rows, + cf[] block.
__global__ void __launch_bounds__(256)
k_convIn(const float* __restrict__ x, const float* __restrict__ w1,
         const float* __restrict__ w2) {
    __shared__ float srow[IN_];
    __shared__ float red[256];
    const int b = blockIdx.x;
    if (b < B_) {
        conv_row_body<IN_, K0P1, true>(x + (long)b * IN_, 1,
            g_ca1 + (long)b * KC1, g_sa1, b, srow, red);
    } else if (b < B_ + NP) {
        const int n = b - B_;
        conv_row_body<IN_, K0P1, false>(w1 + (long)n * IN_, n < H1,
            g_cw1 + (long)n * KC1, g_sw1, n, srow, red);
    } else if (b < B_ + 2 * NP) {
        const int n = b - B_ - NP;
        conv_row_body<H1, K0P2, false>(w2 + (long)n * H1, n < H1,
            g_cw2 + (long)n * KC2, g_sw2, n, srow, red);
    } else {
        if (threadIdx.x < T_) {        // cf[] in fp64 closed form
            const double r = 0.77880078307140487;   // exp(-1/4)
            const double q = 0.36787944117144233;   // exp(-1)
            const double tp1 = (double)(threadIdx.x + 1);
            const double rp = exp(-0.25 * tp1);
            const double qp = exp(-tp1);
            const double c = (r * (1.0 - rp) / (1.0 - r)
                            - q * (1.0 - qp) / (1.0 - q)) / (r - q);
            g_cf[threadIdx.x] = (float)c;
        }
    }
}

__global__ void __launch_bounds__(256) k_cA2() {
    __shared__ float srow[H1];
    __shared__ float red[256];
    const int m = blockIdx.x;
    conv_row_body<H1, K0P2, true>(g_h + (long)m * H1, 1,
        g_ca2 + (long)m * KC2, g_sa2, m, srow, red);
}

// ---------------- HMMA: unified stream, 128-wide steps, 3-stage pipeline ----
// Stage layout (32KB): [A_lo 8K | A_hi 8K | B_lo 8K | B_hi 8K], each 64x128B SW128.
__device__ __forceinline__ void issue_step(const __nv_bfloat16* __restrict__ Ag,
                                           const __nv_bfloat16* __restrict__ Bg,
                                           int KC, int m0, int n0, long koff,
                                           uint32_t stage, int tid) {
#pragma unroll
    for (int i = 0; i < 4; i++) {
        const int e = tid + 256 * i;           // 0..1023
        const int sub = e >> 9;                // 0 or 1 (lo/hi 64 cols)
        const int r = (e & 511) >> 3;          // row 0..63
        const int c8 = e & 7;
        const uint32_t dst = sub * 8192 + SW128((uint32_t)(r * 128 + c8 * 16));
        const long gcol = koff + sub * 64 + c8 * 8;
        cp_async16(stage + dst,         Ag + (long)(m0 + r) * KC + gcol);
        cp_async16(stage + 16384 + dst, Bg + (long)(n0 + r) * KC + gcol);
    }
}

// One combined pass: NSTEP 128-wide steps, per-64-chunk drains to S0/S1.
template<int KC, int NSTEP, int NC0>
__device__ __forceinline__ void gemm_all(const __nv_bfloat16* __restrict__ Ag,
                                         const __nv_bfloat16* __restrict__ Bg,
                                         int m0, int n0,
                                         int wm, int wn, int lane, int tid,
                                         uint32_t smb, float* S0, float* S1) {
    issue_step(Ag, Bg, KC, m0, n0, 0, smb, tid);
    CP_COMMIT();
    issue_step(Ag, Bg, KC, m0, n0, 128, smb + 32768, tid);
    CP_COMMIT();

    for (int s = 0; s < NSTEP; s++) {
        if (s + 1 < NSTEP) { CP_WAIT(1); } else { CP_WAIT(0); }  // tail-safe
        __syncthreads();
        if (s + 2 < NSTEP) {
            issue_step(Ag, Bg, KC, m0, n0, (long)(s + 2) * 128,
                       smb + ((s + 2) % 3) * 32768, tid);
            CP_COMMIT();
        }
        const uint32_t base = smb + (s % 3) * 32768;

#pragma unroll
        for (int half = 0; half < 2; half++) {
            const uint32_t sA = base + half * 8192;
            const uint32_t sB = base + 16384 + half * 8192;

            float acc[4][4];
#pragma unroll
            for (int b = 0; b < 4; b++)
#pragma unroll
                for (int e2 = 0; e2 < 4; e2++) acc[b][e2] = 0.0f;

#pragma unroll
            for (int k16 = 0; k16 < 4; k16++) {
                uint32_t af[4], bf[4][2];
                const int rowa = wm * 16 + (lane & 15);
                const uint32_t kcol = (uint32_t)(k16 * 32 + (lane >> 4) * 16);
                ldm_x4(af[0], af[1], af[2], af[3],
                       sA + SW128((uint32_t)(rowa * 128) + kcol));
                const uint32_t kcolb = (uint32_t)(k16 * 32 + ((lane >> 3) & 1) * 16);
#pragma unroll
                for (int nt = 0; nt < 4; nt++) {
                    const int rowb = wn * 32 + nt * 8 + (lane & 7);
                    ldm_x2(bf[nt][0], bf[nt][1],
                           sB + SW128((uint32_t)(rowb * 128) + kcolb));
                }
#pragma unroll
                for (int nt = 0; nt < 4; nt++)
                    mma16816(acc[nt], af, bf[nt]);
            }
            // drain this 64-chunk (ascending order preserved -> bit-identical)
            float* S = ((2 * s + half) < NC0) ? S0 : S1;
#pragma unroll
            for (int b = 0; b < 4; b++)
#pragma unroll
                for (int e2 = 0; e2 < 4; e2++)
                    S[b * 4 + e2] = __fadd_rn(S[b * 4 + e2], acc[b][e2]);
        }
    }
}

// MODE 1: layer1 (relu -> g_h), MODE 2: layer2 (sigmoid -> g_drive)
template<int MODE>
__global__ void __launch_bounds__(256) k_mma(const float* __restrict__ bias) {
    extern __shared__ char sm[];               // 3 stages x 32KB = 96KB dynamic
    const int tid = threadIdx.x;               // 256
    const int warp = tid >> 5, lane = tid & 31;
    const int wm = warp & 3, wn = warp >> 2;   // 4 M-warps x 2 N-warps
    const int m0 = blockIdx.y * 64, n0 = blockIdx.x * 64;

    float S0[16], S1[16];
#pragma unroll
    for (int i = 0; i < 16; i++) { S0[i] = 0.0f; S1[i] = 0.0f; }

    const uint32_t smb = smem_u32(sm);
    const float *sa, *sw;
    if (MODE == 1) {
        gemm_all<KC1, 39, 13>(g_ca1, g_cw1, m0, n0, wm, wn, lane, tid, smb, S0, S1);
        sa = g_sa1; sw = g_sw1;
    } else {
        gemm_all<KC2, 24, 8>(g_ca2, g_cw2, m0, n0, wm, wn, lane, tid, smb, S0, S1);
        sa = g_sa2; sw = g_sw2;
    }

    // epilogue: v = RN(S0 * 2^(ea+eb-16)) + S1 + bias (pow2 scale mul exact)
#pragma unroll
    for (int nt = 0; nt < 4; nt++) {
        const int gn = n0 + wn * 32 + nt * 8 + (lane & 3) * 2;
#pragma unroll
        for (int rr = 0; rr < 2; rr++) {
            const int m = m0 + wm * 16 + (lane >> 2) + rr * 8;
            const float sam = sa[m];
#pragma unroll
            for (int jj = 0; jj < 2; jj++) {
                const int n = gn + jj;
                if (n >= H1) continue;
                const float sab = sam * sw[n];
                const int idx = nt * 4 + rr * 2 + jj;
                float v = __fadd_rn(__fmul_rn(S0[idx], sab), S1[idx]);
                v = v + bias[n];
                if (MODE == 1) {
                    g_h[(long)m * H1 + n] = fmaxf(v, 0.0f);
                } else {
                    if (v >= 0.0f) v = 1.0f / (1.0f + expf(-v));
                    else { const float e = expf(v); v = e / (1.0f + e); }
                    g_drive[(long)m * H1 + n] = v;
                }
            }
        }
    }
}

// ---------------- fused gemm3 + LIF scan (proven exact) ----------------
__global__ void __launch_bounds__(256, 8)
k_fused3(const float* __restrict__ w3,
         const float* __restrict__ b3,
         float* __restrict__ out) {
    const int m = blockIdx.x;
    __shared__ float row[H1];
    __shared__ float part[250];
    __shared__ float cf[T_];
    __shared__ unsigned sbits[NOUT][4];

    const int tid = threadIdx.x;  // 256
    for (int k = tid; k < H1; k += 256) row[k] = g_drive[m * H1 + k];
    if (tid < T_) cf[tid] = g_cf[tid];
    __syncthreads();

    if (tid < 250) {
        const int n = tid / 25;
        const int ks = (tid % 25) * 20;
        float s = 0.0f;
#pragma unroll
        for (int k = 0; k < 20; k++)
            s = fmaf(row[ks + k], w3[n * H1 + ks + k], s);
        part[tid] = s;
    }
    __syncthreads();

    if (tid < NOUT) {
        float u = 0.0f;
#pragma unroll
        for (int p = 0; p < 25; p++) u += part[tid * 25 + p];

        const float bb = b3[tid];
        const int SIGB = __float_as_int(0.77880078307140487f);
        float v = 0.0f;
        float f = __int_as_float(SIGB);
        unsigned sb0 = 0, sb1 = 0, sb2 = 0, sb3v = 0;
#pragma unroll
        for (int t = 0; t < T_; t++) {
            const float cur = __fadd_rn(__fmul_rn(cf[t], u), bb);
            v = __fadd_rn(__fmul_rn(f, v), cur);
            const int tb = __float_as_int(__fadd_rn(v, -1.0f));
            const int smask = tb >> 31;
            f = __int_as_float(SIGB & smask);
            const unsigned bit = (unsigned)(~smask) & 1u;
            if (t < 32)       sb0 |= bit << t;
            else if (t < 64)  sb1 |= bit << (t - 32);
            else if (t < 96)  sb2 |= bit << (t - 64);
            else              sb3v |= bit << (t - 96);
        }
        sbits[tid][0] = sb0; sbits[tid][1] = sb1;
        sbits[tid][2] = sb2; sbits[tid][3] = sb3v;
    }
    __syncthreads();

    float* oblk = out + (size_t)m * NOUT * T_;
#pragma unroll
    for (int i = tid; i < NOUT * T_; i += 256) {
        const int n = i / T_;
        const int t = i - n * T_;
        const unsigned w = sbits[n][t >> 5];
        oblk[i] = (float)((w >> (t & 31)) & 1u);
    }
}

// ---------------- launch ----------------
extern "C" void kernel_launch(void* const* d_in, const int* in_sizes, int n_in,
                              void* d_out, int out_size) {
    const float* x  = (const float*)d_in[0];
    const float* w1 = (const float*)d_in[1];
    const float* b1 = (const float*)d_in[2];
    const float* w2 = (const float*)d_in[3];
    const float* b2 = (const float*)d_in[4];
    const float* w3 = (const float*)d_in[5];
    const float* b3 = (const float*)d_in[6];
    float* out = (float*)d_out;

    cudaFuncSetAttribute(k_mma<1>, cudaFuncAttributeMaxDynamicSharedMemorySize, 98304);
    cudaFuncSetAttribute(k_mma<2>, cudaFuncAttributeMaxDynamicSharedMemorySize, 98304);

    k_convIn<<<B_ + 2 * NP + 1, 256>>>(x, w1, w2);

    dim3 grid(NP / 64, B_ / 64);               // (8, 16) = 128 CTAs
    k_mma<1><<<grid, 256, 98304>>>(b1);
    k_cA2<<<B_, 256>>>();
    k_mma<2><<<grid, 256, 98304>>>(b2);

    k_fused3<<<B_, 256>>>(w3, b3, out);
}